// round 15
// baseline (speedup 1.0000x reference)
#include <cuda_runtime.h>
#include <cuda_fp16.h>
#include <cstdint>

#define N_ENT   100000
#define N_DRUG  2000
#define N_REL   51
#define N_EDGE  1000000
#define DIM     64
#define BUCKET  64          // per-head capacity; Poisson(10) max over 100K ~35

// fp16 tables (row = 64 halves = 128B = one cache line).
// Rel tables have a leading ZERO row (row 0 never written): pad edge slots
// are packed-0 -> gather ent[0] (valid row) * rel[0] (zeros) -> contribute 0.
__device__ __half2  g_ent0h[N_ENT * 32];
__device__ __half2  g_entA [N_ENT * 32];
__device__ __half2  g_entB [N_ENT * 32];
__device__ __half2  g_rel0z[(N_REL + 1) * 32];   // fp16 rel0, shifted +1
__device__ __half2  g_relnz[(N_REL + 1) * 32];   // fp16 norm(rel0), shifted +1
__device__ int      g_cnt  [N_ENT];
__device__ unsigned g_edges[N_ENT * BUCKET];     // packed: tail | (rel+1)<<17

static __device__ __forceinline__ __half2 u2h(unsigned u) {
    return *reinterpret_cast<__half2*>(&u);
}
static __device__ __forceinline__ unsigned h2u(__half2 h) {
    return *reinterpret_cast<unsigned*>(&h);
}

// ---------------------------------------------------------------------------
// Fused: fp32->fp16 conversion of ent0 (all 1.6M threads, streaming) +
// bucket fill (first 125K threads, 8 edges each, 8 ATOMGs in flight).
// ---------------------------------------------------------------------------
__global__ void prep_kernel(const float4* __restrict__ ent0,
                            const int*    __restrict__ eidx,
                            const int*    __restrict__ etype) {
    int i = blockIdx.x * blockDim.x + threadIdx.x;

    if (i < N_ENT * 16) {
        float4 v = ent0[i];
        uint2 o;
        __half2 h0 = __floats2half2_rn(v.x, v.y);
        __half2 h1 = __floats2half2_rn(v.z, v.w);
        o.x = h2u(h0);
        o.y = h2u(h1);
        reinterpret_cast<uint2*>(g_ent0h)[i] = o;
    }

    if (i < N_EDGE / 8) {
        int base = i * 8;
        #pragma unroll
        for (int k = 0; k < 8; k++) {
            int e  = base + k;
            int h  = eidx[e];
            int tl = eidx[N_EDGE + e];
            int r  = etype[e];
            int pos = atomicAdd(&g_cnt[h], 1);
            if (pos < BUCKET)
                g_edges[(long long)h * BUCKET + pos] =
                    (unsigned)tl | ((unsigned)(r + 1) << 17);
        }
    }
}

// ---------------------------------------------------------------------------
// Relations (once): out_rel = rel0 + 3*normalize(rel0) (norm is idempotent);
// fp16 shifted tables rows 1..N_REL (row 0 stays all-zero).
// ---------------------------------------------------------------------------
__global__ void rel_kernel(const float* __restrict__ rel0,
                           float* __restrict__ out_rel) {
    int row  = blockIdx.x;
    int lane = threadIdx.x;

    float2 v = reinterpret_cast<const float2*>(rel0)[row * 32 + lane];
    float ss = v.x * v.x + v.y * v.y;
    #pragma unroll
    for (int o = 16; o > 0; o >>= 1)
        ss += __shfl_xor_sync(0xFFFFFFFFu, ss, o);

    float inv = 1.0f / fmaxf(sqrtf(ss), 1e-12f);
    float2 n = { v.x * inv, v.y * inv };

    g_rel0z[(row + 1) * 32 + lane] = __float22half2_rn(v);
    g_relnz[(row + 1) * 32 + lane] = __float22half2_rn(n);

    float2 o2 = { v.x + 3.0f * n.x, v.y + 3.0f * n.y };
    reinterpret_cast<float2*>(out_rel)[row * 32 + lane] = o2;
}

// ---------------------------------------------------------------------------
// Fused gather + L2-normalize, fp16 tables. FOUR ROWS PER WARP: 8-lane
// quarter sub=lane>>3 owns row 4w+sub; each lane covers 8 dims via uint4
// (LDG.128; 8 lanes * 16B = full 128B row). Edge words: row's first 32 slots
// = 8 uint4 across the quarter (uint4 index row*16 + q -> slots 4q..4q+3).
// Iteration c pulls 4 edges/row with 4 shfls from holder lane sub*8 + c
// (whose uint4 holds slots 4c..4c+3). Deferred fp16 accumulation (4 running
// half2 per lane), one fp32 conversion after the loop. Pad slots (packed 0)
// hit the rel zero-row -> contribute 0 (no masking, no divergence).
//   final_hop=0: dst[row] = fp16(n)
//   final_hop=1: out_ent = base + entA + entB + n ; ditto drug rows
// ---------------------------------------------------------------------------
__global__ void __launch_bounds__(256)
gather_kernel(const uint4*  __restrict__ ent,   // fp16 table, uint4 = 8 halves
              const uint4*  __restrict__ rel,
              uint4*        __restrict__ dst,
              const float4* __restrict__ base_ent,
              const float4* __restrict__ base_drug,
              float4*       __restrict__ out_ent,
              float4*       __restrict__ out_drug,
              int final_hop) {
    int gw   = (blockIdx.x * blockDim.x + threadIdx.x) >> 5;
    int lane = threadIdx.x & 31;
    int sub  = lane >> 3;       // which row of the quad this group owns
    int q    = lane & 7;        // uint4 index within the row (dims 8q..8q+7)
    int row  = gw * 4 + sub;    // N_ENT % 4 == 0 -> warp-uniform exit
    if (row >= N_ENT) return;

    int deg = g_cnt[row];
    if (deg > BUCKET) deg = BUCKET;

    // row's first 32 edge slots: uint4 index row*16 + q  (BUCKET=64 unsigneds
    // per row = 16 uint4; we use the first 8). FIX vs round 14: was row*8+q.
    uint4 myq = reinterpret_cast<const uint4*>(g_edges)[row * 16 + q];

    int myChunks = ((deg < 32 ? deg : 32) + 3) >> 2;   // 4-edge chunks
    int chunks = myChunks;
    chunks = max(chunks, __shfl_xor_sync(0xFFFFFFFFu, chunks, 8));
    chunks = max(chunks, __shfl_xor_sync(0xFFFFFFFFu, chunks, 16));

    const uint4* entq = ent + q;
    const uint4* relq = rel + q;
    int subbase = sub << 3;

    __half2 ac0 = __float2half2_rn(0.f);
    __half2 ac1 = ac0, ac2 = ac0, ac3 = ac0;

    for (int c = 0; c < chunks; c++) {
        int holder = subbase + c;           // lane holding this chunk's edges
        unsigned p0 = __shfl_sync(0xFFFFFFFFu, myq.x, holder);
        unsigned p1 = __shfl_sync(0xFFFFFFFFu, myq.y, holder);
        unsigned p2 = __shfl_sync(0xFFFFFFFFu, myq.z, holder);
        unsigned p3 = __shfl_sync(0xFFFFFFFFu, myq.w, holder);

        uint4 a0 = entq[(p0 & 0x1FFFFu) * 8];
        uint4 b0 = relq[(p0 >> 17)      * 8];
        uint4 a1 = entq[(p1 & 0x1FFFFu) * 8];
        uint4 b1 = relq[(p1 >> 17)      * 8];
        uint4 a2 = entq[(p2 & 0x1FFFFu) * 8];
        uint4 b2 = relq[(p2 >> 17)      * 8];
        uint4 a3 = entq[(p3 & 0x1FFFFu) * 8];
        uint4 b3 = relq[(p3 >> 17)      * 8];

        ac0 = __hfma2(u2h(a0.x), u2h(b0.x), ac0);
        ac1 = __hfma2(u2h(a0.y), u2h(b0.y), ac1);
        ac2 = __hfma2(u2h(a0.z), u2h(b0.z), ac2);
        ac3 = __hfma2(u2h(a0.w), u2h(b0.w), ac3);
        ac0 = __hfma2(u2h(a1.x), u2h(b1.x), ac0);
        ac1 = __hfma2(u2h(a1.y), u2h(b1.y), ac1);
        ac2 = __hfma2(u2h(a1.z), u2h(b1.z), ac2);
        ac3 = __hfma2(u2h(a1.w), u2h(b1.w), ac3);
        ac0 = __hfma2(u2h(a2.x), u2h(b2.x), ac0);
        ac1 = __hfma2(u2h(a2.y), u2h(b2.y), ac1);
        ac2 = __hfma2(u2h(a2.z), u2h(b2.z), ac2);
        ac3 = __hfma2(u2h(a2.w), u2h(b2.w), ac3);
        ac0 = __hfma2(u2h(a3.x), u2h(b3.x), ac0);
        ac1 = __hfma2(u2h(a3.y), u2h(b3.y), ac1);
        ac2 = __hfma2(u2h(a3.z), u2h(b3.z), ac2);
        ac3 = __hfma2(u2h(a3.w), u2h(b3.w), ac3);
    }

    float2 u0 = __half22float2(ac0);
    float2 u1 = __half22float2(ac1);
    float2 u2 = __half22float2(ac2);
    float2 u3 = __half22float2(ac3);
    float f0 = u0.x, f1 = u0.y, f2 = u1.x, f3 = u1.y;
    float f4 = u2.x, f5 = u2.y, f6 = u3.x, f7 = u3.y;

    // ultra-rare tail (deg > 32), fp32 path, per-quarter
    for (int t = 32; t < deg; t++) {
        unsigned p = g_edges[(long long)row * BUCKET + t];
        uint4 a = entq[(p & 0x1FFFFu) * 8];
        uint4 b = relq[(p >> 17)      * 8];
        float2 pa, pb;
        pa = __half22float2(u2h(a.x)); pb = __half22float2(u2h(b.x));
        f0 += pa.x * pb.x; f1 += pa.y * pb.y;
        pa = __half22float2(u2h(a.y)); pb = __half22float2(u2h(b.y));
        f2 += pa.x * pb.x; f3 += pa.y * pb.y;
        pa = __half22float2(u2h(a.z)); pb = __half22float2(u2h(b.z));
        f4 += pa.x * pb.x; f5 += pa.y * pb.y;
        pa = __half22float2(u2h(a.w)); pb = __half22float2(u2h(b.w));
        f6 += pa.x * pb.x; f7 += pa.y * pb.y;
    }

    // reduce within the 8-lane quarter (xor offsets 1,2,4 stay inside)
    float ss = f0 * f0 + f1 * f1 + f2 * f2 + f3 * f3
             + f4 * f4 + f5 * f5 + f6 * f6 + f7 * f7;
    #pragma unroll
    for (int o = 4; o > 0; o >>= 1)
        ss += __shfl_xor_sync(0xFFFFFFFFu, ss, o);

    float inv = rsqrtf(fmaxf(ss, 1e-24f));   // == 1/max(sqrt(ss),1e-12)
    f0 *= inv; f1 *= inv; f2 *= inv; f3 *= inv;
    f4 *= inv; f5 *= inv; f6 *= inv; f7 *= inv;

    long long idx = (long long)row * 8 + q;   // uint4 index in fp16 tables

    if (!final_hop) {
        uint4 o;
        o.x = h2u(__floats2half2_rn(f0, f1));
        o.y = h2u(__floats2half2_rn(f2, f3));
        o.z = h2u(__floats2half2_rn(f4, f5));
        o.w = h2u(__floats2half2_rn(f6, f7));
        dst[idx] = o;
    } else {
        uint4 ha = reinterpret_cast<const uint4*>(g_entA)[idx];
        uint4 hb = reinterpret_cast<const uint4*>(g_entB)[idx];
        float2 x0, x1, y0, y1;

        long long fidx = (long long)row * 16 + q * 2;  // float4 index

        x0 = __half22float2(u2h(ha.x)); y0 = __half22float2(u2h(hb.x));
        x1 = __half22float2(u2h(ha.y)); y1 = __half22float2(u2h(hb.y));
        {
            float sx = x0.x + y0.x + f0;
            float sy = x0.y + y0.y + f1;
            float sz = x1.x + y1.x + f2;
            float sw = x1.y + y1.y + f3;
            float4 e0 = base_ent[fidx];
            out_ent[fidx] = make_float4(e0.x + sx, e0.y + sy,
                                        e0.z + sz, e0.w + sw);
            if (row < N_DRUG) {
                float4 d0 = base_drug[fidx];
                out_drug[fidx] = make_float4(d0.x + sx, d0.y + sy,
                                             d0.z + sz, d0.w + sw);
            }
        }
        x0 = __half22float2(u2h(ha.z)); y0 = __half22float2(u2h(hb.z));
        x1 = __half22float2(u2h(ha.w)); y1 = __half22float2(u2h(hb.w));
        {
            float sx = x0.x + y0.x + f4;
            float sy = x0.y + y0.y + f5;
            float sz = x1.x + y1.x + f6;
            float sw = x1.y + y1.y + f7;
            float4 e0 = base_ent[fidx + 1];
            out_ent[fidx + 1] = make_float4(e0.x + sx, e0.y + sy,
                                            e0.z + sz, e0.w + sw);
            if (row < N_DRUG) {
                float4 d0 = base_drug[fidx + 1];
                out_drug[fidx + 1] = make_float4(d0.x + sx, d0.y + sy,
                                                 d0.z + sz, d0.w + sw);
            }
        }
    }
}

// ---------------------------------------------------------------------------
extern "C" void kernel_launch(void* const* d_in, const int* in_sizes, int n_in,
                              void* d_out, int out_size) {
    const float* ent0  = (const float*)d_in[0];
    const float* drug0 = (const float*)d_in[1];
    const float* rel0  = (const float*)d_in[2];
    const int*   eidx  = (const int*)d_in[3];
    const int*   etype = (const int*)d_in[4];

    float* out      = (float*)d_out;
    float* out_ent  = out;
    float* out_drug = out + (size_t)N_ENT * DIM;
    float* out_rel  = out + (size_t)(N_ENT + N_DRUG) * DIM;

    void *p0, *pA, *pB, *pR0, *pRN, *pC;
    cudaGetSymbolAddress(&p0,  g_ent0h);
    cudaGetSymbolAddress(&pA,  g_entA);
    cudaGetSymbolAddress(&pB,  g_entB);
    cudaGetSymbolAddress(&pR0, g_rel0z);
    cudaGetSymbolAddress(&pRN, g_relnz);
    cudaGetSymbolAddress(&pC,  g_cnt);

    // counters reset + fused conv/fill + relation tables
    cudaMemsetAsync(pC, 0, N_ENT * sizeof(int), 0);
    prep_kernel<<<(N_ENT * 16 + 255) / 256, 256>>>(
        (const float4*)ent0, eidx, etype);
    rel_kernel<<<N_REL, 32>>>(rel0, out_rel);

    // 4 rows per warp -> N_ENT/4 warps
    const int warps  = N_ENT / 4;
    const int blocks = (warps * 32 + 255) / 256;

    // hop 0: fp16(ent0) * rel0 -> entA
    gather_kernel<<<blocks, 256>>>(
        (const uint4*)p0, (const uint4*)pR0, (uint4*)pA,
        nullptr, nullptr, nullptr, nullptr, 0);
    // hop 1: entA * norm(rel) -> entB
    gather_kernel<<<blocks, 256>>>(
        (const uint4*)pA, (const uint4*)pRN, (uint4*)pB,
        nullptr, nullptr, nullptr, nullptr, 0);
    // hop 2 (final): entB * norm(rel) -> n3; out = base + entA + entB + n3
    gather_kernel<<<blocks, 256>>>(
        (const uint4*)pB, (const uint4*)pRN, nullptr,
        (const float4*)ent0, (const float4*)drug0,
        (float4*)out_ent, (float4*)out_drug, 1);
}